// round 4
// baseline (speedup 1.0000x reference)
#include <cuda_runtime.h>
#include <cstdint>
#include <cstdio>

// Problem constants
#define B_ 2
#define S_ 2048
#define D_ 4096
#define H_ 16
#define HD_ 256
#define NQKV 12288            // 3*D
#define MROWS 4096            // B*S
#define GK 4096               // GEMM K for both GEMMs
#define NCHUNK (GK / 32)

// ---------------- scratch (device globals: no allocation allowed) ----------
__device__ float g_WqkvT[(size_t)NQKV * D_]; // 192 MB  (W^T: [N,K] K-major)
__device__ float g_qkv  [(size_t)MROWS * NQKV];// 192 MB
__device__ float g_WoutT[(size_t)D_ * D_];   // 64 MB
__device__ float g_ctx  [(size_t)MROWS * D_];// 64 MB

__device__ __forceinline__ uint32_t f2tf32(float x) {
    uint32_t r; asm("cvt.rna.tf32.f32 %0, %1;" : "=r"(r) : "f"(x)); return r;
}

// ---------------- GPTQ 4-bit dequant -> transposed W^T [N, K] --------------
__global__ void dequant_t_kernel(const int* __restrict__ qw, const int* __restrict__ qz,
                                 const float* __restrict__ sc, float* __restrict__ Wt, int N) {
    size_t idx = (size_t)blockIdx.x * blockDim.x + threadIdx.x;
    size_t total = (size_t)(D_ / 8) * (size_t)N;
    if (idx >= total) return;
    int n = (int)(idx % N);
    int r = (int)(idx / N);          // packed row: k = r*8 .. r*8+7
    int g = r >> 4;                  // group index (GS=128 => 16 packed rows/group)
    unsigned w = (unsigned)qw[(size_t)r * N + n];
    unsigned z = (unsigned)qz[(size_t)g * (N / 8) + (n >> 3)];
    int zp = (int)((z >> ((n & 7) * 4)) & 15u) + 1;
    float s = sc[(size_t)g * N + n];
    float v[8];
#pragma unroll
    for (int j = 0; j < 8; j++)
        v[j] = s * (float)((int)((w >> (j * 4)) & 15u) - zp);
    float* dst = Wt + (size_t)n * D_ + (size_t)r * 8;
    *(float4*)dst       = make_float4(v[0], v[1], v[2], v[3]);
    *(float4*)(dst + 4) = make_float4(v[4], v[5], v[6], v[7]);
}

// ---------------- tf32 mma.sync GEMM: C[M,N] = A[M,K] @ Bt[N,K]^T -----------
// 128 threads (4 warps, 2x2 grid of 64x64 warp tiles), block tile 128x128,
// BK=32, double-buffered SMEM staged in mma-fragment order.
//
// Fragment maps (PTX mma.m16n8k8.tf32):
//   A(m,k): lane=(m&7)*4+(k&3), reg=(m%16>=8 ? 1:0)+(k%8>=4 ? 2:0)
//   B(k,n): lane=(n&7)*4+(k&3), reg=(k%8>=4 ? 1:0)
// SMEM word layout:
//   A: [stage][mtile(8)*kstep(4)][lane(32)][reg(4)]  -> 4096 words/stage
//   B: [stage][ntile(16)*kstep(4)][lane(32)][reg(2)] -> 4096 words/stage
__global__ __launch_bounds__(128) void tf32_gemm(const float* __restrict__ A,
                                                 const float* __restrict__ Bt,
                                                 float* __restrict__ C, int N) {
    extern __shared__ uint32_t sm[];            // [A0 A1 B0 B1], 4 x 4096 words
    const int tid = threadIdx.x;
    const int wid = tid >> 5;
    const int lane = tid & 31;
    const int wm = wid >> 1;       // 0..1 : 64-row half
    const int wn = wid & 1;        // 0..1 : 64-col half
    const int bx = blockIdx.x, by = blockIdx.y;

    const float* Ag = A + (size_t)(by * 128) * GK;
    const float* Bg = Bt + (size_t)(bx * 128) * GK;

    auto load_tile = [&](int kc, int st) {
        uint32_t* sA = sm + st * 4096;
        uint32_t* sB = sm + 8192 + st * 4096;
        const float* Ap = Ag + kc * 32;
        const float* Bp = Bg + kc * 32;
#pragma unroll
        for (int i = 0; i < 8; i++) {
            int flat = tid + i * 128;          // 0..1023
            int r = flat >> 3;                 // 0..127 (row of A / row of Bt)
            int c4 = (flat & 7) * 4;           // k offset 0..28
            float4 va = *(const float4*)(Ap + (size_t)r * GK + c4);
            float4 vb = *(const float4*)(Bp + (size_t)r * GK + c4);
            // A: m=r, k=c4+j
            int mtile = r >> 4, row16 = r & 15;
            int kstep = c4 >> 3;
            int rega = ((c4 & 4) ? 2 : 0) + ((row16 & 8) ? 1 : 0);
            uint32_t* pa = sA + (((mtile * 4 + kstep) * 32) + (row16 & 7) * 4) * 4 + rega;
            pa[0]  = f2tf32(va.x);
            pa[4]  = f2tf32(va.y);
            pa[8]  = f2tf32(va.z);
            pa[12] = f2tf32(va.w);
            // B: n=r, k=c4+j
            int ntile = r >> 3, col8 = r & 7;
            int regb = (c4 & 4) ? 1 : 0;
            uint32_t* pb = sB + (((ntile * 4 + kstep) * 32) + col8 * 4) * 2 + regb;
            pb[0] = f2tf32(vb.x);
            pb[2] = f2tf32(vb.y);
            pb[4] = f2tf32(vb.z);
            pb[6] = f2tf32(vb.w);
        }
    };

    float acc[4][8][4];
#pragma unroll
    for (int mt = 0; mt < 4; mt++)
#pragma unroll
        for (int nt = 0; nt < 8; nt++)
#pragma unroll
            for (int j = 0; j < 4; j++) acc[mt][nt][j] = 0.f;

    load_tile(0, 0);
    __syncthreads();

#pragma unroll 1
    for (int i = 0; i < NCHUNK; i++) {
        if (i + 1 < NCHUNK) load_tile(i + 1, (i + 1) & 1);
        const uint32_t* sA = sm + (i & 1) * 4096;
        const uint32_t* sB = sm + 8192 + (i & 1) * 4096;
#pragma unroll
        for (int ks = 0; ks < 4; ks++) {
            uint32_t a[4][4];
#pragma unroll
            for (int mt = 0; mt < 4; mt++) {
                uint4 v = *(const uint4*)(sA + (((wm * 4 + mt) * 4 + ks) * 32 + lane) * 4);
                a[mt][0] = v.x; a[mt][1] = v.y; a[mt][2] = v.z; a[mt][3] = v.w;
            }
            uint32_t b[8][2];
#pragma unroll
            for (int nt = 0; nt < 8; nt++) {
                uint2 v = *(const uint2*)(sB + (((wn * 8 + nt) * 4 + ks) * 32 + lane) * 2);
                b[nt][0] = v.x; b[nt][1] = v.y;
            }
#pragma unroll
            for (int mt = 0; mt < 4; mt++)
#pragma unroll
                for (int nt = 0; nt < 8; nt++) {
                    asm volatile(
                        "mma.sync.aligned.m16n8k8.row.col.f32.tf32.tf32.f32 "
                        "{%0,%1,%2,%3}, {%4,%5,%6,%7}, {%8,%9}, {%0,%1,%2,%3};"
                        : "+f"(acc[mt][nt][0]), "+f"(acc[mt][nt][1]),
                          "+f"(acc[mt][nt][2]), "+f"(acc[mt][nt][3])
                        : "r"(a[mt][0]), "r"(a[mt][1]), "r"(a[mt][2]), "r"(a[mt][3]),
                          "r"(b[nt][0]), "r"(b[nt][1]));
                }
        }
        __syncthreads();
    }

    // epilogue: C(m,n). c0:(r, c) c1:(r, c+1) c2:(r+8, c) c3:(r+8, c+1)
    const int row0 = by * 128 + wm * 64 + (lane >> 2);
    const int col0 = bx * 128 + wn * 64 + (lane & 3) * 2;
#pragma unroll
    for (int mt = 0; mt < 4; mt++) {
#pragma unroll
        for (int nt = 0; nt < 8; nt++) {
            float* p0 = C + (size_t)(row0 + mt * 16) * N + col0 + nt * 8;
            float* p1 = p0 + (size_t)8 * N;
            *(float2*)p0 = make_float2(acc[mt][nt][0], acc[mt][nt][1]);
            *(float2*)p1 = make_float2(acc[mt][nt][2], acc[mt][nt][3]);
        }
    }
}

// ---------------- RoPE (GPT-J interleaved, first 64 dims of q and k) -------
__global__ void rope_kernel(float* __restrict__ qkv) {
    int bs = blockIdx.x;
    int s = bs & (S_ - 1);
    int h = threadIdx.x >> 5;
    int i = threadIdx.x & 31;
    float inv_freq = 1.0f / powf(10000.0f, (float)(2 * i) / 64.0f);
    float ang = (float)s * inv_freq;
    float sn = sinf(ang), cs = cosf(ang);
    size_t base = (size_t)bs * NQKV + (size_t)h * HD_ + 2 * i;
    float* q = qkv + base;
    float* k = qkv + base + D_;
    float q0 = q[0], q1 = q[1];
    q[0] = q0 * cs - q1 * sn;
    q[1] = q1 * cs + q0 * sn;
    float k0 = k[0], k1 = k[1];
    k[0] = k0 * cs - k1 * sn;
    k[1] = k1 * cs + k0 * sn;
}

// ---------------- causal flash attention (fp32) -----------------------------
#define SWZ(d, c) ((d) ^ ((c) << 2))

__global__ __launch_bounds__(256) void attn_kernel(const float* __restrict__ qkv,
                                                   float* __restrict__ ctx) {
    extern __shared__ float smf[];
    float* Ks = smf;
    float* Vs = smf + 32 * 256;
    const int tid = threadIdx.x;
    const int ql = tid >> 3;
    const int c = tid & 7;
    const int bh = blockIdx.y;
    const int b = bh >> 4;
    const int h = bh & 15;
    const int qg = blockIdx.x * 32 + ql;
    const float* base = qkv + (size_t)b * S_ * NQKV;

    float qreg[32], o[32], s[32];
    const float* qrow = base + (size_t)qg * NQKV + h * HD_ + c * 32;
#pragma unroll
    for (int t = 0; t < 8; t++) {
        float4 v = *(const float4*)(qrow + 4 * t);
        qreg[4 * t] = v.x; qreg[4 * t + 1] = v.y;
        qreg[4 * t + 2] = v.z; qreg[4 * t + 3] = v.w;
    }
#pragma unroll
    for (int j = 0; j < 32; j++) o[j] = 0.f;
    float m = -1e30f, l = 0.f;

    const int nt = blockIdx.x + 1;
    for (int kt = 0; kt < nt; kt++) {
        const int k0 = kt * 32;
        __syncthreads();
#pragma unroll
        for (int i = 0; i < 8; i++) {
            int f = tid + i * 256;
            int r = f >> 6;
            int cc = (f & 63) * 4;
            int pc = cc ^ ((((unsigned)cc >> 5) & 7) << 2);
            const float* kg = base + (size_t)(k0 + r) * NQKV + D_ + h * HD_ + cc;
            *(float4*)&Ks[r * 256 + pc] = *(const float4*)kg;
            *(float4*)&Vs[r * 256 + pc] = *(const float4*)(kg + D_);
        }
        __syncthreads();

#pragma unroll
        for (int kk = 0; kk < 32; kk++) s[kk] = 0.f;
#pragma unroll
        for (int t = 0; t < 8; t++) {
            const int dph = SWZ(c * 32 + t * 4, c);
            float a0 = qreg[4 * t], a1 = qreg[4 * t + 1];
            float a2 = qreg[4 * t + 2], a3 = qreg[4 * t + 3];
#pragma unroll
            for (int kk = 0; kk < 32; kk++) {
                float4 kv = *(const float4*)&Ks[kk * 256 + dph];
                s[kk] += a0 * kv.x + a1 * kv.y + a2 * kv.z + a3 * kv.w;
            }
        }
#pragma unroll
        for (int kk = 0; kk < 32; kk++) {
            float v = s[kk];
            v += __shfl_xor_sync(0xffffffffu, v, 1);
            v += __shfl_xor_sync(0xffffffffu, v, 2);
            v += __shfl_xor_sync(0xffffffffu, v, 4);
            s[kk] = v * 0.0625f;
        }
        if (kt == nt - 1) {
#pragma unroll
            for (int kk = 0; kk < 32; kk++)
                if (k0 + kk > qg) s[kk] = -1e30f;
        }
        float mt = m;
#pragma unroll
        for (int kk = 0; kk < 32; kk++) mt = fmaxf(mt, s[kk]);
        float resc = __expf(m - mt);
        l *= resc;
#pragma unroll
        for (int j = 0; j < 32; j++) o[j] *= resc;
#pragma unroll
        for (int kk = 0; kk < 32; kk++) {
            s[kk] = __expf(s[kk] - mt);
            l += s[kk];
        }
        m = mt;
#pragma unroll
        for (int t = 0; t < 8; t++) {
            const int dph = SWZ(c * 32 + t * 4, c);
            float a0 = 0.f, a1 = 0.f, a2 = 0.f, a3 = 0.f;
#pragma unroll
            for (int kk = 0; kk < 32; kk++) {
                float4 vv = *(const float4*)&Vs[kk * 256 + dph];
                a0 += s[kk] * vv.x; a1 += s[kk] * vv.y;
                a2 += s[kk] * vv.z; a3 += s[kk] * vv.w;
            }
            o[4 * t] += a0; o[4 * t + 1] += a1;
            o[4 * t + 2] += a2; o[4 * t + 3] += a3;
        }
    }
    float invl = 1.f / l;
    float* outp = ctx + (size_t)(b * S_ + qg) * D_ + h * HD_ + c * 32;
#pragma unroll
    for (int t = 0; t < 8; t++) {
        float4 v = make_float4(o[4 * t] * invl, o[4 * t + 1] * invl,
                               o[4 * t + 2] * invl, o[4 * t + 3] * invl);
        *(float4*)(outp + 4 * t) = v;
    }
}

// ---------------- launch ----------------------------------------------------
extern "C" void kernel_launch(void* const* d_in, const int* in_sizes, int n_in,
                              void* d_out, int out_size) {
    const float* hs     = (const float*)d_in[0];
    const int*   qw_qkv = (const int*)  d_in[1];
    const int*   qz_qkv = (const int*)  d_in[2];
    const float* sc_qkv = (const float*)d_in[3];
    const int*   qw_out = (const int*)  d_in[4];
    const int*   qz_out = (const int*)  d_in[5];
    const float* sc_out = (const float*)d_in[6];
    float* out = (float*)d_out;

    float *WqkvT, *qkv, *WoutT, *ctx;
    cudaGetSymbolAddress((void**)&WqkvT, g_WqkvT);
    cudaGetSymbolAddress((void**)&qkv,   g_qkv);
    cudaGetSymbolAddress((void**)&WoutT, g_WoutT);
    cudaGetSymbolAddress((void**)&ctx,   g_ctx);

    const int gemm_smem = 4 * 4096 * 4;   // 64 KB
    cudaFuncSetAttribute(tf32_gemm,
                         cudaFuncAttributeMaxDynamicSharedMemorySize, gemm_smem);
    cudaFuncSetAttribute(attn_kernel,
                         cudaFuncAttributeMaxDynamicSharedMemorySize, 65536);

    // 1) dequant both weights into transposed [N, K] layout
    dequant_t_kernel<<<(D_ / 8) * (NQKV / 256), 256>>>(qw_qkv, qz_qkv, sc_qkv, WqkvT, NQKV);
    dequant_t_kernel<<<(D_ / 8) * (D_   / 256), 256>>>(qw_out, qz_out, sc_out, WoutT, D_);

    // 2) QKV GEMM (tf32 tensor cores): [4096,4096] @ W^T[12288,4096]
    dim3 g1(NQKV / 128, MROWS / 128);
    tf32_gemm<<<g1, 128, gemm_smem>>>(hs, WqkvT, qkv, NQKV);

    // 3) RoPE in-place on q,k
    rope_kernel<<<B_ * S_, H_ * 32>>>(qkv);

    // 4) causal flash attention -> ctx
    dim3 g2(S_ / 32, B_ * H_);
    attn_kernel<<<g2, 256, 65536>>>(qkv, ctx);

    // 5) output GEMM (tf32 tensor cores) -> d_out
    dim3 g3(D_ / 128, MROWS / 128);
    tf32_gemm<<<g3, 128, gemm_smem>>>(ctx, WoutT, out, D_);
}

// round 5
// speedup vs baseline: 1.4119x; 1.4119x over previous
#include <cuda_runtime.h>
#include <cstdint>

#define B_ 2
#define S_ 2048
#define D_ 4096
#define NQKV 12288
#define MROWS 4096

// ---------------- scratch ----------------------------------------------------
__device__ float g_WqkvT[(size_t)NQKV * D_];
__device__ float g_qkv  [(size_t)MROWS * NQKV];
__device__ float g_WoutT[(size_t)D_ * D_];
__device__ float g_ctx  [(size_t)MROWS * D_];
__device__ float g_hs32 [(size_t)MROWS * D_];

__device__ __forceinline__ uint32_t smem_u32(const void* p) {
    uint32_t a;
    asm("{ .reg .u64 t; cvta.to.shared.u64 t, %1; cvt.u32.u64 %0, t; }" : "=r"(a) : "l"(p));
    return a;
}
__device__ __forceinline__ float tf32f(float x) {
    uint32_t r; asm("cvt.rna.tf32.f32 %0, %1;" : "=r"(r) : "f"(x));
    return __uint_as_float(r);
}
__device__ __forceinline__ void ldsm4(uint32_t& r0, uint32_t& r1, uint32_t& r2,
                                      uint32_t& r3, uint32_t addr) {
    asm volatile("ldmatrix.sync.aligned.m8n8.x4.shared.b16 {%0,%1,%2,%3}, [%4];"
                 : "=r"(r0), "=r"(r1), "=r"(r2), "=r"(r3) : "r"(addr));
}
#define CPA16(dst, src) \
    asm volatile("cp.async.cg.shared.global [%0], [%1], 16;" :: "r"(dst), "l"(src))
#define MMA8(d, a, b0_, b1_) \
    asm volatile("mma.sync.aligned.m16n8k8.row.col.f32.tf32.tf32.f32 " \
                 "{%0,%1,%2,%3}, {%4,%5,%6,%7}, {%8,%9}, {%0,%1,%2,%3};" \
                 : "+f"(d[0]), "+f"(d[1]), "+f"(d[2]), "+f"(d[3]) \
                 : "r"(a[0]), "r"(a[1]), "r"(a[2]), "r"(a[3]), "r"(b0_), "r"(b1_))

// ---------------- GPTQ 4-bit dequant -> W^T [N,K], tf32-rounded -------------
__global__ void dequant_t_kernel(const int* __restrict__ qw, const int* __restrict__ qz,
                                 const float* __restrict__ sc, float* __restrict__ Wt, int N) {
    size_t idx = (size_t)blockIdx.x * blockDim.x + threadIdx.x;
    if (idx >= (size_t)(D_ / 8) * N) return;
    int n = (int)(idx % N);
    int r = (int)(idx / N);
    int g = r >> 4;
    unsigned w = (unsigned)qw[(size_t)r * N + n];
    unsigned z = (unsigned)qz[(size_t)g * (N / 8) + (n >> 3)];
    int zp = (int)((z >> ((n & 7) * 4)) & 15u) + 1;
    float s = sc[(size_t)g * N + n];
    float v[8];
#pragma unroll
    for (int j = 0; j < 8; j++)
        v[j] = tf32f(s * (float)((int)((w >> (j * 4)) & 15u) - zp));
    float* dst = Wt + (size_t)n * D_ + (size_t)r * 8;
    *(float4*)dst       = make_float4(v[0], v[1], v[2], v[3]);
    *(float4*)(dst + 4) = make_float4(v[4], v[5], v[6], v[7]);
}

__global__ void tf32_copy_kernel(const float4* __restrict__ src, float4* __restrict__ dst) {
    size_t i = (size_t)blockIdx.x * blockDim.x + threadIdx.x;
    float4 v = src[i];
    dst[i] = make_float4(tf32f(v.x), tf32f(v.y), tf32f(v.z), tf32f(v.w));
}

// ---------------- tf32 mma GEMM v2: C[M,N] = A[M,K] @ Bt[N,K]^T --------------
// 256 thr, 8 warps (2Mx4N), block 128x256, warp 64x64, BK=32, 3-stage cp.async.
#define STG 49152
__global__ __launch_bounds__(256, 1) void tf32_gemm(const float* __restrict__ A,
                                                    const float* __restrict__ Bt,
                                                    float* __restrict__ C, int N) {
    extern __shared__ char smraw[];
    const uint32_t sb = smem_u32(smraw);
    const int tid = threadIdx.x;
    const int L = tid & 31;
    const int wid = tid >> 5;
    const int wm = wid >> 2, wn = wid & 3;

    const float* Ag = A + (size_t)(blockIdx.y * 128) * 4096;
    const float* Bg = Bt + (size_t)(blockIdx.x * 256) * 4096;

    auto stage_load = [&](int kc, int st) {
        uint32_t sA = sb + st * STG;
        uint32_t sB = sA + 16384;
        const float* Ap = Ag + kc * 32;
        const float* Bp = Bg + kc * 32;
#pragma unroll
        for (int i = 0; i < 4; i++) {
            int f = tid + i * 256, r = f >> 3, c = f & 7;
            CPA16(sA + r * 128 + ((c * 16) ^ ((r & 7) << 4)), Ap + (size_t)r * 4096 + c * 4);
        }
#pragma unroll
        for (int i = 0; i < 8; i++) {
            int f = tid + i * 256, r = f >> 3, c = f & 7;
            CPA16(sB + r * 128 + ((c * 16) ^ ((r & 7) << 4)), Bp + (size_t)r * 4096 + c * 4);
        }
        asm volatile("cp.async.commit_group;" ::: "memory");
    };

    float acc[4][8][4];
#pragma unroll
    for (int mt = 0; mt < 4; mt++)
#pragma unroll
        for (int nt = 0; nt < 8; nt++)
#pragma unroll
            for (int j = 0; j < 4; j++) acc[mt][nt][j] = 0.f;

    stage_load(0, 0);
    stage_load(1, 1);

#pragma unroll 1
    for (int i = 0; i < 128; i++) {
        if (i < 127) asm volatile("cp.async.wait_group 1;" ::: "memory");
        else         asm volatile("cp.async.wait_group 0;" ::: "memory");
        __syncthreads();
        if (i + 2 < 128) stage_load(i + 2, (i + 2) % 3);
        uint32_t sA = sb + (i % 3) * STG;
        uint32_t sB = sA + 16384;
#pragma unroll
        for (int ks = 0; ks < 4; ks++) {
            uint32_t a[4][4];
#pragma unroll
            for (int mt = 0; mt < 4; mt++) {
                int row = wm * 64 + mt * 16 + (L & 15);
                ldsm4(a[mt][0], a[mt][1], a[mt][2], a[mt][3],
                      sA + row * 128 + (((2 * ks + (L >> 4)) * 16) ^ ((row & 7) << 4)));
            }
#pragma unroll
            for (int np = 0; np < 4; np++) {
                int n = wn * 64 + np * 16 + ((L & 7) | ((L & 16) >> 1));
                uint32_t b0, b1, b2, b3;
                ldsm4(b0, b1, b2, b3,
                      sB + n * 128 + (((2 * ks + ((L >> 3) & 1)) * 16) ^ ((n & 7) << 4)));
#pragma unroll
                for (int mt = 0; mt < 4; mt++) {
                    MMA8(acc[mt][2 * np], a[mt], b0, b1);
                    MMA8(acc[mt][2 * np + 1], a[mt], b2, b3);
                }
            }
        }
    }

    const int row0 = blockIdx.y * 128 + wm * 64 + (L >> 2);
    const int col0 = blockIdx.x * 256 + wn * 64 + 2 * (L & 3);
#pragma unroll
    for (int mt = 0; mt < 4; mt++)
#pragma unroll
        for (int nt = 0; nt < 8; nt++) {
            float* p = C + (size_t)(row0 + mt * 16) * N + col0 + nt * 8;
            *(float2*)p = make_float2(acc[mt][nt][0], acc[mt][nt][1]);
            *(float2*)(p + (size_t)8 * N) = make_float2(acc[mt][nt][2], acc[mt][nt][3]);
        }
}

// ---------------- RoPE -------------------------------------------------------
__global__ void rope_kernel(float* __restrict__ qkv) {
    int bs = blockIdx.x;
    int s = bs & (S_ - 1);
    int h = threadIdx.x >> 5;
    int i = threadIdx.x & 31;
    float inv_freq = 1.0f / powf(10000.0f, (float)(2 * i) / 64.0f);
    float ang = (float)s * inv_freq;
    float sn = sinf(ang), cs = cosf(ang);
    size_t base = (size_t)bs * NQKV + (size_t)h * 256 + 2 * i;
    float* q = qkv + base;
    float* k = qkv + base + D_;
    float q0 = q[0], q1 = q[1];
    q[0] = q0 * cs - q1 * sn;
    q[1] = q1 * cs + q0 * sn;
    float k0 = k[0], k1 = k[1];
    k[0] = k0 * cs - k1 * sn;
    k[1] = k1 * cs + k0 * sn;
}

// ---------------- causal flash attention (fp32, unchanged) -------------------
#define SWZ(d, c) ((d) ^ ((c) << 2))
__global__ __launch_bounds__(256) void attn_kernel(const float* __restrict__ qkv,
                                                   float* __restrict__ ctx) {
    extern __shared__ float smf[];
    float* Ks = smf;
    float* Vs = smf + 32 * 256;
    const int tid = threadIdx.x;
    const int ql = tid >> 3;
    const int c = tid & 7;
    const int b = blockIdx.y >> 4, h = blockIdx.y & 15;
    const int qg = blockIdx.x * 32 + ql;
    const float* base = qkv + (size_t)b * S_ * NQKV;

    float qreg[32], o[32], s[32];
    const float* qrow = base + (size_t)qg * NQKV + h * 256 + c * 32;
#pragma unroll
    for (int t = 0; t < 8; t++) {
        float4 v = *(const float4*)(qrow + 4 * t);
        qreg[4 * t] = v.x; qreg[4 * t + 1] = v.y;
        qreg[4 * t + 2] = v.z; qreg[4 * t + 3] = v.w;
    }
#pragma unroll
    for (int j = 0; j < 32; j++) o[j] = 0.f;
    float m = -1e30f, l = 0.f;

    const int nt = blockIdx.x + 1;
    for (int kt = 0; kt < nt; kt++) {
        const int k0 = kt * 32;
        __syncthreads();
#pragma unroll
        for (int i = 0; i < 8; i++) {
            int f = tid + i * 256;
            int r = f >> 6;
            int cc = (f & 63) * 4;
            int pc = cc ^ ((((unsigned)cc >> 5) & 7) << 2);
            const float* kg = base + (size_t)(k0 + r) * NQKV + D_ + h * 256 + cc;
            *(float4*)&Ks[r * 256 + pc] = *(const float4*)kg;
            *(float4*)&Vs[r * 256 + pc] = *(const float4*)(kg + D_);
        }
        __syncthreads();
#pragma unroll
        for (int kk = 0; kk < 32; kk++) s[kk] = 0.f;
#pragma unroll
        for (int t = 0; t < 8; t++) {
            const int dph = SWZ(c * 32 + t * 4, c);
            float a0 = qreg[4 * t], a1 = qreg[4 * t + 1];
            float a2 = qreg[4 * t + 2], a3 = qreg[4 * t + 3];
#pragma unroll
            for (int kk = 0; kk < 32; kk++) {
                float4 kv = *(const float4*)&Ks[kk * 256 + dph];
                s[kk] += a0 * kv.x + a1 * kv.y + a2 * kv.z + a3 * kv.w;
            }
        }
#pragma unroll
        for (int kk = 0; kk < 32; kk++) {
            float v = s[kk];
            v += __shfl_xor_sync(0xffffffffu, v, 1);
            v += __shfl_xor_sync(0xffffffffu, v, 2);
            v += __shfl_xor_sync(0xffffffffu, v, 4);
            s[kk] = v * 0.0625f;
        }
        if (kt == nt - 1) {
#pragma unroll
            for (int kk = 0; kk < 32; kk++)
                if (k0 + kk > qg) s[kk] = -1e30f;
        }
        float mt = m;
#pragma unroll
        for (int kk = 0; kk < 32; kk++) mt = fmaxf(mt, s[kk]);
        float resc = __expf(m - mt);
        l *= resc;
#pragma unroll
        for (int j = 0; j < 32; j++) o[j] *= resc;
#pragma unroll
        for (int kk = 0; kk < 32; kk++) {
            s[kk] = __expf(s[kk] - mt);
            l += s[kk];
        }
        m = mt;
#pragma unroll
        for (int t = 0; t < 8; t++) {
            const int dph = SWZ(c * 32 + t * 4, c);
            float a0 = 0.f, a1 = 0.f, a2 = 0.f, a3 = 0.f;
#pragma unroll
            for (int kk = 0; kk < 32; kk++) {
                float4 vv = *(const float4*)&Vs[kk * 256 + dph];
                a0 += s[kk] * vv.x; a1 += s[kk] * vv.y;
                a2 += s[kk] * vv.z; a3 += s[kk] * vv.w;
            }
            o[4 * t] += a0; o[4 * t + 1] += a1;
            o[4 * t + 2] += a2; o[4 * t + 3] += a3;
        }
    }
    float invl = 1.f / l;
    float* outp = ctx + (size_t)(b * S_ + qg) * D_ + h * 256 + c * 32;
#pragma unroll
    for (int t = 0; t < 8; t++) {
        float4 v = make_float4(tf32f(o[4 * t] * invl), tf32f(o[4 * t + 1] * invl),
                               tf32f(o[4 * t + 2] * invl), tf32f(o[4 * t + 3] * invl));
        *(float4*)(outp + 4 * t) = v;
    }
}

// ---------------- launch ------------------------------------------------------
extern "C" void kernel_launch(void* const* d_in, const int* in_sizes, int n_in,
                              void* d_out, int out_size) {
    const float* hs     = (const float*)d_in[0];
    const int*   qw_qkv = (const int*)  d_in[1];
    const int*   qz_qkv = (const int*)  d_in[2];
    const float* sc_qkv = (const float*)d_in[3];
    const int*   qw_out = (const int*)  d_in[4];
    const int*   qz_out = (const int*)  d_in[5];
    const float* sc_out = (const float*)d_in[6];
    float* out = (float*)d_out;

    float *WqkvT, *qkv, *WoutT, *ctx, *hs32;
    cudaGetSymbolAddress((void**)&WqkvT, g_WqkvT);
    cudaGetSymbolAddress((void**)&qkv,   g_qkv);
    cudaGetSymbolAddress((void**)&WoutT, g_WoutT);
    cudaGetSymbolAddress((void**)&ctx,   g_ctx);
    cudaGetSymbolAddress((void**)&hs32,  g_hs32);

    cudaFuncSetAttribute(tf32_gemm,
                         cudaFuncAttributeMaxDynamicSharedMemorySize, 3 * STG);
    cudaFuncSetAttribute(attn_kernel,
                         cudaFuncAttributeMaxDynamicSharedMemorySize, 65536);

    dequant_t_kernel<<<(D_ / 8) * (NQKV / 256), 256>>>(qw_qkv, qz_qkv, sc_qkv, WqkvT, NQKV);
    dequant_t_kernel<<<(D_ / 8) * (D_   / 256), 256>>>(qw_out, qz_out, sc_out, WoutT, D_);
    tf32_copy_kernel<<<(MROWS * (D_ / 4)) / 256, 256>>>((const float4*)hs, (float4*)hs32);

    dim3 g1(NQKV / 256, MROWS / 128);
    tf32_gemm<<<g1, 256, 3 * STG>>>(hs32, WqkvT, qkv, NQKV);

    rope_kernel<<<B_ * S_, 512>>>(qkv);

    dim3 g2(S_ / 32, 32);
    attn_kernel<<<g2, 256, 65536>>>(qkv, ctx);

    dim3 g3(D_ / 256, MROWS / 128);
    tf32_gemm<<<g3, 256, 3 * STG>>>(ctx, WoutT, out, D_);
}